// round 6
// baseline (speedup 1.0000x reference)
#include <cuda_runtime.h>
#include <cuda_bf16.h>

#define FULLMASK 0xffffffffu

__device__ float g_losses[256];

// One CTA = 128 threads = 4 warps, TWO batches:
//   warps 0,1 (SMSP 0,1) -> batch 2*bid,  warps 2,3 (SMSP 2,3) -> batch 2*bid+1
// Within a batch-group (64 threads), thread lt owns columns (2*lt, 2*lt+1)
// over the FULL i-range; expT slice in registers (128 bf16x2).
// One __syncthreads per step; rescale piggybacks on e[0] (no extra barriers).
__global__ void __launch_bounds__(128, 1) k_crf_forward(
    const float* __restrict__ feats,   // [B,S,L]
    const float* __restrict__ startT,  // [L]
    const float* __restrict__ endT,    // [L]
    const float* __restrict__ trans,   // [L,L]
    const float* __restrict__ conf,    // [B]
    const int*   __restrict__ mask,    // [B,S]
    const int*   __restrict__ labels,  // [B,S]
    int S)
{
    constexpr int L = 128;
    extern __shared__ char sm[];
    // ebuf[group][phase][64] packed bf16x2
    unsigned* ebuf  = (unsigned*)sm;                       // 2*2*64*4 = 1024B
    int*      smask = (int*)(sm + 1024);                   // [2][S]
    float*    sred  = (float*)(sm + 1024 + 2 * S * 4);     // [2][2] + scratch

    const int tid = threadIdx.x;
    const int g   = tid >> 6;          // batch group 0/1
    const int lt  = tid & 63;          // lane within group
    const int wg  = (tid >> 5) & 1;    // warp within group
    const int b   = 2 * blockIdx.x + g;
    const int c0  = 2 * lt;
    const int c1  = 2 * lt + 1;

    const float*  fb  = feats + (size_t)b * S * L;
    const float2* fb2 = (const float2*)fb;            // [S][64]

    unsigned* myebuf = ebuf + g * 128;                 // this group's 2 phases

    // ---- expT slices into registers: 64 bf16x2 per owned column ----
    __nv_bfloat162 T0[64], T1[64];
    #pragma unroll
    for (int k = 0; k < 64; ++k) {
        const float* r0 = trans + (size_t)(2 * k) * L;
        const float* r1 = trans + (size_t)(2 * k + 1) * L;
        T0[k] = __floats2bfloat162_rn(__expf(__ldg(r0 + c0)), __expf(__ldg(r1 + c0)));
        T1[k] = __floats2bfloat162_rn(__expf(__ldg(r0 + c1)), __expf(__ldg(r1 + c1)));
    }
    for (int k = lt; k < S; k += 64) smask[g * S + k] = mask[b * S + k];

    // ---- alpha0 ----
    float a00 = startT[c0] + fb[c0];
    float a01 = startT[c1] + fb[c1];
    __syncthreads();                       // smask ready
    // group max (2 warps)
    float mv = fmaxf(a00, a01);
    #pragma unroll
    for (int o = 16; o; o >>= 1) mv = fmaxf(mv, __shfl_xor_sync(FULLMASK, mv, o));
    if ((tid & 31) == 0) sred[2 * g + wg] = mv;
    __syncthreads();
    float m0 = fmaxf(sred[2 * g], sred[2 * g + 1]);
    __syncthreads();

    float v0 = __expf(a00 - m0);
    float v1 = __expf(a01 - m0);
    float offset = m0;                     // alpha = offset + log(v)
    { __nv_bfloat162 pk = __floats2bfloat162_rn(v0, v1); myebuf[64 + lt] = *(unsigned*)&pk; }

    float2 fA = fb2[64 + lt];                               // feat(t=1)
    float2 fB = (S > 2) ? fb2[2 * 64 + lt] : make_float2(0.f, 0.f);
    __syncthreads();

    const __nv_bfloat162 bz = __floats2bfloat162_rn(0.f, 0.f);

    for (int t = 1; t < S; ++t) {
        const uint4* se = (const uint4*)(myebuf + (t & 1) * 64);  // read phase
        unsigned*    wbp = myebuf + ((t & 1) ^ 1) * 64;           // write phase

        __nv_bfloat162 a0 = bz, a1 = bz, a2 = bz, a3 = bz;        // col c0
        __nv_bfloat162 b0 = bz, b1 = bz, b2 = bz, b3 = bz;        // col c1
        float e0f = 1.0f;
        #pragma unroll
        for (int p = 0; p < 16; ++p) {
            uint4 q = se[p];                       // e[8p .. 8p+7]
            __nv_bfloat162 q0 = *(__nv_bfloat162*)&q.x;
            __nv_bfloat162 q1 = *(__nv_bfloat162*)&q.y;
            __nv_bfloat162 q2 = *(__nv_bfloat162*)&q.z;
            __nv_bfloat162 q3 = *(__nv_bfloat162*)&q.w;
            if (p == 0) e0f = __low2float(q0);     // e[0]: free normalizer
            a0 = __hfma2(q0, T0[4 * p + 0], a0);
            a1 = __hfma2(q1, T0[4 * p + 1], a1);
            a2 = __hfma2(q2, T0[4 * p + 2], a2);
            a3 = __hfma2(q3, T0[4 * p + 3], a3);
            b0 = __hfma2(q0, T1[4 * p + 0], b0);
            b1 = __hfma2(q1, T1[4 * p + 1], b1);
            b2 = __hfma2(q2, T1[4 * p + 2], b2);
            b3 = __hfma2(q3, T1[4 * p + 3], b3);
        }
        a0 = __hadd2(a0, a1); a2 = __hadd2(a2, a3); a0 = __hadd2(a0, a2);
        b0 = __hadd2(b0, b1); b2 = __hadd2(b2, b3); b0 = __hadd2(b0, b2);
        float s0 = __low2float(a0) + __high2float(a0);
        float s1 = __low2float(b0) + __high2float(b0);

        float2 fcur = fA;
        fA = fB;
        if (t + 2 < S) fB = fb2[(size_t)(t + 2) * 64 + lt];   // prefetch

        if (smask[g * S + t]) {
            v0 = s0 * __expf(fcur.x);
            v1 = s1 * __expf(fcur.y);
            if ((t & 3) == 0) {   // uniform rescale by e[0], exactly accounted
                float r = __frcp_rn(e0f);
                v0 *= r; v1 *= r;
                offset += __logf(e0f);
            }
        }
        // else masked: alpha (v0,v1) carries over unchanged

        __nv_bfloat162 pk = __floats2bfloat162_rn(v0, v1);
        wbp[lt] = *(unsigned*)&pk;
        __syncthreads();
    }

    // ---- denominator: group sum (2 warps) ----
    float contrib = v0 * __expf(endT[c0]) + v1 * __expf(endT[c1]);
    #pragma unroll
    for (int o = 16; o; o >>= 1) contrib += __shfl_xor_sync(FULLMASK, contrib, o);
    if ((tid & 31) == 0) sred[2 * g + wg] = contrib;
    __syncthreads();
    float log_den = offset + __logf(sred[2 * g] + sred[2 * g + 1]);
    __syncthreads();

    // ---- numerator: label-path score (exact fp32) ----
    float num = 0.f;
    float slf = 0.f;
    const int* lb = labels + b * S;
    for (int k = lt; k < S; k += 64) {
        int mk = smask[g * S + k];
        slf += (float)mk;
        int lab = lb[k]; if (lab == -100) lab = 0;
        if (k == 0) {
            num += startT[lab] + fb[lab];
        } else if (mk) {
            int lp = lb[k - 1]; if (lp == -100) lp = 0;
            num += trans[lp * L + lab] + fb[(size_t)k * L + lab];
        }
    }
    #pragma unroll
    for (int o = 16; o; o >>= 1) {
        num += __shfl_xor_sync(FULLMASK, num, o);
        slf += __shfl_xor_sync(FULLMASK, slf, o);
    }
    if ((tid & 31) == 0) { sred[2 * g + wg] = num; sred[4 + 2 * g + wg] = slf; }
    __syncthreads();
    num = sred[2 * g] + sred[2 * g + 1];
    slf = sred[4 + 2 * g] + sred[4 + 2 * g + 1];

    int lastt = (int)(slf + 0.5f) - 1;
    if (lastt < 0) lastt = 0;
    int lastlab = lb[lastt]; if (lastlab == -100) lastlab = 0;
    num += endT[lastlab];

    if (lt == 0) g_losses[b] = (log_den - num) * conf[b];
}

__global__ void k_finalize(float* __restrict__ out, int B) {
    int t = threadIdx.x;
    float x = (t < B) ? g_losses[t] : 0.f;
    #pragma unroll
    for (int o = 16; o; o >>= 1) x += __shfl_xor_sync(FULLMASK, x, o);
    __shared__ float sh[8];
    if ((t & 31) == 0) sh[t >> 5] = x;
    __syncthreads();
    if (t == 0) {
        float s = 0.f;
        int nw = (blockDim.x + 31) >> 5;
        for (int w = 0; w < nw; ++w) s += sh[w];
        out[0] = s / (float)B;
    }
}

extern "C" void kernel_launch(void* const* d_in, const int* in_sizes, int n_in,
                              void* d_out, int out_size) {
    const float* feats  = (const float*)d_in[0];
    const float* startT = (const float*)d_in[1];
    const float* endT   = (const float*)d_in[2];
    const float* trans  = (const float*)d_in[3];
    const float* conf   = (const float*)d_in[4];
    const int*   mask   = (const int*)  d_in[5];
    const int*   labels = (const int*)  d_in[6];

    const int B = in_sizes[4];            // 256
    const int S = in_sizes[5] / B;        // 512
    (void)n_in; (void)out_size;

    size_t smem = 1024                    // 2 groups x double-buffered e vecs
                + (size_t)2 * S * 4       // masks for both batches
                + 64;                     // reduction scratch

    k_crf_forward<<<B / 2, 128, smem>>>(feats, startT, endT, trans, conf,
                                        mask, labels, S);
    k_finalize<<<1, 256>>>((float*)d_out, B);
}